// round 2
// baseline (speedup 1.0000x reference)
#include <cuda_runtime.h>
#include <cstdint>

#define B_  8
#define L_  1024
#define D_  768
#define H_  12
#define DH_ 64
#define NEG_BIG (-1e30f)

// Scratch (allocation-free rule: __device__ globals)
__device__ float g_K [B_ * L_ * D_];   // K projection, [b, l, d]
__device__ float g_wV[B_ * L_ * D_];   // attention output, [b, l, d]

// ---------------------------------------------------------------------------
// GEMM: C[M,N] = A[M,K] * B[N,K]^T + bias[N]
// Block tile 128(M) x 64(N), TK=16, 256 threads, 8x4 micro-tile.
// ---------------------------------------------------------------------------
__global__ __launch_bounds__(256)
void gemm_nt_bias(const float* __restrict__ A, const float* __restrict__ Bm,
                  const float* __restrict__ bias, float* __restrict__ C,
                  int M, int N, int K) {
    __shared__ float As[16 * 132];   // [k][m], pad 132 -> aligned float4 reads
    __shared__ float Bs[16 * 68];    // [k][n], pad 68  -> aligned float4 reads

    const int m0 = blockIdx.y * 128;
    const int n0 = blockIdx.x * 64;
    const int tid = threadIdx.x;
    const int tx = tid & 15;         // n direction (4 cols)
    const int ty = tid >> 4;         // m direction (8 rows)
    const int lk = tid & 15;         // loader: k index
    const int lr = tid >> 4;         // loader: row base

    float acc[8][4];
#pragma unroll
    for (int i = 0; i < 8; i++)
#pragma unroll
        for (int j = 0; j < 4; j++) acc[i][j] = 0.f;

    for (int k0 = 0; k0 < K; k0 += 16) {
#pragma unroll
        for (int i = 0; i < 8; i++) {
            int m = lr + i * 16;
            As[lk * 132 + m] = A[(size_t)(m0 + m) * K + k0 + lk];
        }
#pragma unroll
        for (int i = 0; i < 4; i++) {
            int n = lr + i * 16;
            Bs[lk * 68 + n] = Bm[(size_t)(n0 + n) * K + k0 + lk];
        }
        __syncthreads();

#pragma unroll
        for (int kk = 0; kk < 16; kk++) {
            float4 a0 = *(const float4*)&As[kk * 132 + ty * 8];
            float4 a1 = *(const float4*)&As[kk * 132 + ty * 8 + 4];
            float4 b4 = *(const float4*)&Bs[kk * 68 + tx * 4];
            float av[8] = {a0.x, a0.y, a0.z, a0.w, a1.x, a1.y, a1.z, a1.w};
            float bv[4] = {b4.x, b4.y, b4.z, b4.w};
#pragma unroll
            for (int i = 0; i < 8; i++)
#pragma unroll
                for (int j = 0; j < 4; j++)
                    acc[i][j] = fmaf(av[i], bv[j], acc[i][j]);
        }
        __syncthreads();
    }

    float4 bv4 = *(const float4*)&bias[n0 + tx * 4];
    float bb[4] = {bv4.x, bv4.y, bv4.z, bv4.w};
#pragma unroll
    for (int i = 0; i < 8; i++) {
        int m = m0 + ty * 8 + i;
        float4 r = make_float4(acc[i][0] + bb[0], acc[i][1] + bb[1],
                               acc[i][2] + bb[2], acc[i][3] + bb[3]);
        *(float4*)&C[(size_t)m * N + n0 + tx * 4] = r;
    }
}

// ---------------------------------------------------------------------------
// Fused flash attention per (b, h): S = Kh Kh^T / sqrt(768), row mask,
// online softmax, O = P @ Kh. 128 query rows per CTA, 64-key tiles.
// Dynamic SMEM: QsT[64][132] + KsT[64][68] + Ks[64][68] + Ps[128][64]
// ---------------------------------------------------------------------------
#define ATTN_SMEM_FLOATS (64 * 132 + 64 * 68 + 64 * 68 + 128 * 64)
#define ATTN_SMEM_BYTES  (ATTN_SMEM_FLOATS * 4)

__global__ __launch_bounds__(256, 2)
void attn_kernel(const float* __restrict__ gK, const int* __restrict__ mask,
                 float* __restrict__ out) {
    extern __shared__ float sm[];
    float* QsT = sm;                       // [d][q]  64 x 132
    float* KsT = QsT + 64 * 132;           // [d][k]  64 x 68
    float* Ksm = KsT + 64 * 68;            // [k][d]  64 x 68
    float* Ps  = Ksm + 64 * 68;            // [q][k] 128 x 64
    __shared__ int mrow[128];

    const int q0 = blockIdx.x * 128;
    const int h  = blockIdx.y;
    const int b  = blockIdx.z;
    const int tid = threadIdx.x;
    const int tx = tid & 15;               // k-col / d-col group (4 wide)
    const int ty = tid >> 4;               // q-row group (8 rows)

    const float* Kb = gK + ((size_t)b * L_) * D_ + h * DH_;

    // Load Q tile transposed: QsT[d][q]
    {
        int d = tid & 63, q = tid >> 6;    // q in 0..3
#pragma unroll
        for (int i = 0; i < 32; i++) {
            int qq = q + i * 4;
            QsT[d * 132 + qq] = Kb[(size_t)(q0 + qq) * D_ + d];
        }
    }
    if (tid < 128) mrow[tid] = mask[b * L_ + q0 + tid];
    __syncthreads();

    float m_i[8], l_i[8], o[8][4];
#pragma unroll
    for (int i = 0; i < 8; i++) {
        m_i[i] = NEG_BIG; l_i[i] = 0.f;
#pragma unroll
        for (int j = 0; j < 4; j++) o[i][j] = 0.f;
    }
    bool rmask[8];
#pragma unroll
    for (int i = 0; i < 8; i++) rmask[i] = (mrow[ty * 8 + i] == 0);

    const float scale = 0.03608439182435161f;   // 1/sqrt(768)

    for (int kt = 0; kt < L_; kt += 64) {
        __syncthreads();   // protect Ks/KsT/Ps from previous iteration readers
        {
            int d = tid & 63, k = tid >> 6;
#pragma unroll
            for (int i = 0; i < 16; i++) {
                int kk = k + i * 4;
                float v = Kb[(size_t)(kt + kk) * D_ + d];
                Ksm[kk * 68 + d] = v;
                KsT[d * 68 + kk] = v;
            }
        }
        __syncthreads();

        // ---- S = Q K^T (8x4 micro) ----
        float s[8][4];
#pragma unroll
        for (int i = 0; i < 8; i++)
#pragma unroll
            for (int j = 0; j < 4; j++) s[i][j] = 0.f;

#pragma unroll 4
        for (int d = 0; d < 64; d++) {
            float4 a0 = *(const float4*)&QsT[d * 132 + ty * 8];
            float4 a1 = *(const float4*)&QsT[d * 132 + ty * 8 + 4];
            float4 b4 = *(const float4*)&KsT[d * 68 + tx * 4];
            float av[8] = {a0.x, a0.y, a0.z, a0.w, a1.x, a1.y, a1.z, a1.w};
            float bv[4] = {b4.x, b4.y, b4.z, b4.w};
#pragma unroll
            for (int i = 0; i < 8; i++)
#pragma unroll
                for (int j = 0; j < 4; j++)
                    s[i][j] = fmaf(av[i], bv[j], s[i][j]);
        }

        // ---- online softmax + stage P ----
#pragma unroll
        for (int i = 0; i < 8; i++) {
            float rm = NEG_BIG;
#pragma unroll
            for (int j = 0; j < 4; j++) {
                s[i][j] = rmask[i] ? -1e9f : s[i][j] * scale;
                rm = fmaxf(rm, s[i][j]);
            }
            rm = fmaxf(rm, __shfl_xor_sync(0xffffffffu, rm, 1));
            rm = fmaxf(rm, __shfl_xor_sync(0xffffffffu, rm, 2));
            rm = fmaxf(rm, __shfl_xor_sync(0xffffffffu, rm, 4));
            rm = fmaxf(rm, __shfl_xor_sync(0xffffffffu, rm, 8));
            float nm   = fmaxf(m_i[i], rm);
            float corr = __expf(m_i[i] - nm);
            m_i[i] = nm;
            float ps = 0.f;
#pragma unroll
            for (int j = 0; j < 4; j++) {
                s[i][j] = __expf(s[i][j] - nm);
                ps += s[i][j];
            }
            ps += __shfl_xor_sync(0xffffffffu, ps, 1);
            ps += __shfl_xor_sync(0xffffffffu, ps, 2);
            ps += __shfl_xor_sync(0xffffffffu, ps, 4);
            ps += __shfl_xor_sync(0xffffffffu, ps, 8);
            l_i[i] = l_i[i] * corr + ps;
#pragma unroll
            for (int j = 0; j < 4; j++) o[i][j] *= corr;
            *(float4*)&Ps[(ty * 8 + i) * 64 + tx * 4] =
                make_float4(s[i][0], s[i][1], s[i][2], s[i][3]);
        }
        __syncthreads();

        // ---- O += P @ V (V = K tile), k unrolled by 4 ----
#pragma unroll 2
        for (int k = 0; k < 64; k += 4) {
            float4 v0 = *(const float4*)&Ksm[(k + 0) * 68 + tx * 4];
            float4 v1 = *(const float4*)&Ksm[(k + 1) * 68 + tx * 4];
            float4 v2 = *(const float4*)&Ksm[(k + 2) * 68 + tx * 4];
            float4 v3 = *(const float4*)&Ksm[(k + 3) * 68 + tx * 4];
#pragma unroll
            for (int i = 0; i < 8; i++) {
                float4 p4 = *(const float4*)&Ps[(ty * 8 + i) * 64 + k];
                o[i][0] = fmaf(p4.x, v0.x, o[i][0]);
                o[i][1] = fmaf(p4.x, v0.y, o[i][1]);
                o[i][2] = fmaf(p4.x, v0.z, o[i][2]);
                o[i][3] = fmaf(p4.x, v0.w, o[i][3]);
                o[i][0] = fmaf(p4.y, v1.x, o[i][0]);
                o[i][1] = fmaf(p4.y, v1.y, o[i][1]);
                o[i][2] = fmaf(p4.y, v1.z, o[i][2]);
                o[i][3] = fmaf(p4.y, v1.w, o[i][3]);
                o[i][0] = fmaf(p4.z, v2.x, o[i][0]);
                o[i][1] = fmaf(p4.z, v2.y, o[i][1]);
                o[i][2] = fmaf(p4.z, v2.z, o[i][2]);
                o[i][3] = fmaf(p4.z, v2.w, o[i][3]);
                o[i][0] = fmaf(p4.w, v3.x, o[i][0]);
                o[i][1] = fmaf(p4.w, v3.y, o[i][1]);
                o[i][2] = fmaf(p4.w, v3.z, o[i][2]);
                o[i][3] = fmaf(p4.w, v3.w, o[i][3]);
            }
        }
    }

    // Epilogue: normalize and scatter into [b, l, h*64 + d]
#pragma unroll
    for (int i = 0; i < 8; i++) {
        float inv = 1.0f / l_i[i];
        int q = q0 + ty * 8 + i;
        float4 r = make_float4(o[i][0] * inv, o[i][1] * inv,
                               o[i][2] * inv, o[i][3] * inv);
        *(float4*)&out[((size_t)b * L_ + q) * D_ + h * DH_ + tx * 4] = r;
    }
}

// ---------------------------------------------------------------------------
// Launch. Inputs: 0:x 1:attention_mask 2:Wq 3:bq 4:Wk 5:bk 6:Wv 7:bv 8:Wo 9:bo
// Q projection and (Wv,bv) are dead in the reference (V = K, scores = K K^T).
// ---------------------------------------------------------------------------
extern "C" void kernel_launch(void* const* d_in, const int* in_sizes, int n_in,
                              void* d_out, int out_size) {
    const float* x    = (const float*)d_in[0];
    const int*   mask = (const int*)  d_in[1];
    const float* Wk   = (const float*)d_in[4];
    const float* bk   = (const float*)d_in[5];
    const float* Wo   = (const float*)d_in[8];
    const float* bo   = (const float*)d_in[9];
    float* out = (float*)d_out;

    float *pK = nullptr, *pwV = nullptr;
    cudaGetSymbolAddress((void**)&pK,  g_K);
    cudaGetSymbolAddress((void**)&pwV, g_wV);

    cudaFuncSetAttribute(attn_kernel,
                         cudaFuncAttributeMaxDynamicSharedMemorySize,
                         ATTN_SMEM_BYTES);

    const int M = B_ * L_;   // 8192

    // 1) K = x @ Wk^T + bk
    {
        dim3 grid(D_ / 64, M / 128);
        gemm_nt_bias<<<grid, 256>>>(x, Wk, bk, pK, M, D_, D_);
    }
    // 2) fused attention (scores = Kh Kh^T / sqrt(768), V = Kh)
    {
        dim3 grid(L_ / 128, H_, B_);
        attn_kernel<<<grid, 256, ATTN_SMEM_BYTES>>>(pK, mask, pwV);
    }
    // 3) out = wV @ Wo^T + bo
    {
        dim3 grid(D_ / 64, M / 128);
        gemm_nt_bias<<<grid, 256>>>(pwV, Wo, bo, out, M, D_, D_);
    }
}

// round 6
// speedup vs baseline: 1.3483x; 1.3483x over previous
#include <cuda_runtime.h>
#include <cuda_bf16.h>
#include <cstdint>

#define B_  8
#define L_  1024
#define D_  768
#define H_  12
#define DH_ 64
#define NEG_BIG (-1e30f)

// ---------------- scratch (__device__ globals; no allocation allowed) ------
__device__ float g_K  [B_ * L_ * D_];            // K projection, fp32
__device__ float g_wV [B_ * L_ * D_];            // attention output, fp32
__device__ __nv_bfloat16 g_xhi [B_ * L_ * D_];   // split of x
__device__ __nv_bfloat16 g_xlo [B_ * L_ * D_];
__device__ __nv_bfloat16 g_vhi [B_ * L_ * D_];   // split of wV
__device__ __nv_bfloat16 g_vlo [B_ * L_ * D_];
__device__ __nv_bfloat16 g_wkhi[D_ * D_];
__device__ __nv_bfloat16 g_wklo[D_ * D_];
__device__ __nv_bfloat16 g_wohi[D_ * D_];
__device__ __nv_bfloat16 g_wolo[D_ * D_];

// ---------------------------------------------------------------------------
// split: fp32 -> (hi bf16, lo bf16), lo = bf16(v - float(hi))
// ---------------------------------------------------------------------------
__global__ void split_fp32(const float* __restrict__ in,
                           __nv_bfloat16* __restrict__ hi,
                           __nv_bfloat16* __restrict__ lo, int n4) {
    int i = blockIdx.x * blockDim.x + threadIdx.x;
    if (i >= n4) return;
    float4 v = ((const float4*)in)[i];
    __nv_bfloat16 hx = __float2bfloat16_rn(v.x);
    __nv_bfloat16 hy = __float2bfloat16_rn(v.y);
    __nv_bfloat16 hz = __float2bfloat16_rn(v.z);
    __nv_bfloat16 hw = __float2bfloat16_rn(v.w);
    __nv_bfloat162* hp = (__nv_bfloat162*)(hi + i * 4);
    hp[0] = __nv_bfloat162(hx, hy);
    hp[1] = __nv_bfloat162(hz, hw);
    __nv_bfloat162* lp = (__nv_bfloat162*)(lo + i * 4);
    lp[0] = __nv_bfloat162(__float2bfloat16_rn(v.x - __bfloat162float(hx)),
                           __float2bfloat16_rn(v.y - __bfloat162float(hy)));
    lp[1] = __nv_bfloat162(__float2bfloat16_rn(v.z - __bfloat162float(hz)),
                           __float2bfloat16_rn(v.w - __bfloat162float(hw)));
}

// ---------------------------------------------------------------------------
// mma.sync helpers (arch-agnostic PTX; compiles for plain sm_103 target)
// ---------------------------------------------------------------------------
__device__ __forceinline__ uint32_t smem_u32(const void* p) {
    uint32_t a;
    asm("{ .reg .u64 t; cvta.to.shared.u64 t, %1; cvt.u32.u64 %0, t; }"
        : "=r"(a) : "l"(p));
    return a;
}
__device__ __forceinline__ void ldsm_x4(uint32_t* r, uint32_t addr) {
    asm volatile("ldmatrix.sync.aligned.m8n8.x4.shared.b16 {%0,%1,%2,%3}, [%4];"
                 : "=r"(r[0]), "=r"(r[1]), "=r"(r[2]), "=r"(r[3]) : "r"(addr));
}
__device__ __forceinline__ void ldsm_x2(uint32_t* r, uint32_t addr) {
    asm volatile("ldmatrix.sync.aligned.m8n8.x2.shared.b16 {%0,%1}, [%2];"
                 : "=r"(r[0]), "=r"(r[1]) : "r"(addr));
}
__device__ __forceinline__ void mma_bf16(float* c, const uint32_t* a,
                                         const uint32_t* b) {
    asm volatile(
        "mma.sync.aligned.m16n8k16.row.col.f32.bf16.bf16.f32 "
        "{%0,%1,%2,%3}, {%4,%5,%6,%7}, {%8,%9}, {%0,%1,%2,%3};"
        : "+f"(c[0]), "+f"(c[1]), "+f"(c[2]), "+f"(c[3])
        : "r"(a[0]), "r"(a[1]), "r"(a[2]), "r"(a[3]), "r"(b[0]), "r"(b[1]));
}
#define CP_ASYNC16(saddr, gaddr) \
    asm volatile("cp.async.ca.shared.global [%0], [%1], 16;" \
                 :: "r"(saddr), "l"(gaddr) : "memory")
#define CP_COMMIT() asm volatile("cp.async.commit_group;" ::: "memory")
#define CP_WAIT(n)  asm volatile("cp.async.wait_group %0;" :: "n"(n) : "memory")

// ---------------------------------------------------------------------------
// split-bf16 tensor-core GEMM: C[M,768] = A[M,768] * W[768,768]^T + bias
// CTA 128x128, K-block 32 bf16, 256 thr (8 warps, 2Mx4N), double-buffered.
// SMEM rows padded to 40 bf16 (80 B) -> conflict-free ldmatrix.
// ---------------------------------------------------------------------------
#define GKD    768
#define GROWB  80                      // bytes per SMEM row
#define GOFF_AHI 0
#define GOFF_ALO 10240
#define GOFF_BHI 20480
#define GOFF_BLO 30720
#define GBUF   40960
#define GSMEM_TOTAL (2 * GBUF)

__global__ __launch_bounds__(256)
void gemm_mma_split(const __nv_bfloat16* __restrict__ Ahi,
                    const __nv_bfloat16* __restrict__ Alo,
                    const __nv_bfloat16* __restrict__ Bhi,
                    const __nv_bfloat16* __restrict__ Blo,
                    const float* __restrict__ bias,
                    float* __restrict__ C) {
    extern __shared__ char smc[];
    const uint32_t sb = smem_u32(smc);
    const int tid  = threadIdx.x;
    const int lane = tid & 31;
    const int wid  = tid >> 5;
    const int wm   = wid & 1;          // warp M index (2)
    const int wn   = wid >> 1;         // warp N index (4)
    const int m0 = blockIdx.y * 128;
    const int n0 = blockIdx.x * 128;

    const char* gp[4] = {
        (const char*)(Ahi + (size_t)m0 * GKD),
        (const char*)(Alo + (size_t)m0 * GKD),
        (const char*)(Bhi + (size_t)n0 * GKD),
        (const char*)(Blo + (size_t)n0 * GKD)};
    const uint32_t soff[4] = {GOFF_AHI, GOFF_ALO, GOFF_BHI, GOFF_BLO};

    // loader indices: 512 16B-chunks per matrix, 2 per thread
    const int r0c = (tid * 2) >> 2, c0c = (tid * 2) & 3;
    const int r1c = (tid * 2 + 1) >> 2, c1c = (tid * 2 + 1) & 3;

#define GISSUE(kb, buf) do {                                                   \
    const uint32_t bb = sb + (buf) * GBUF;                                     \
    _Pragma("unroll")                                                          \
    for (int mat = 0; mat < 4; mat++) {                                        \
        CP_ASYNC16(bb + soff[mat] + r0c * GROWB + c0c * 16,                    \
                   gp[mat] + (size_t)r0c * (GKD * 2) + (kb) * 64 + c0c * 16);  \
        CP_ASYNC16(bb + soff[mat] + r1c * GROWB + c1c * 16,                    \
                   gp[mat] + (size_t)r1c * (GKD * 2) + (kb) * 64 + c1c * 16);  \
    }                                                                          \
    CP_COMMIT();                                                               \
} while (0)

    float acc[4][4][4];
#pragma unroll
    for (int mt = 0; mt < 4; mt++)
#pragma unroll
        for (int nt = 0; nt < 4; nt++)
#pragma unroll
            for (int k = 0; k < 4; k++) acc[mt][nt][k] = 0.f;

    // ldmatrix lane addressing (within a buffer)
    const uint32_t a_row  = wm * 64 + (lane & 15);
    const uint32_t a_koff = (lane >> 4) << 4;           // 0 or 16 bytes
    const uint32_t b_row  = wn * 32 + (lane & 7);
    const uint32_t b_koff = ((lane >> 3) & 1) << 4;     // lanes 0-15 used

    GISSUE(0, 0);

    for (int kb = 0; kb < GKD / 32; kb++) {
        const int buf = kb & 1;
        if (kb + 1 < GKD / 32) {
            GISSUE(kb + 1, buf ^ 1);
            CP_WAIT(1);
        } else {
            CP_WAIT(0);
        }
        __syncthreads();

        const uint32_t bb = sb + buf * GBUF;
#pragma unroll
        for (int kk = 0; kk < 2; kk++) {
            const uint32_t ka = kk * 32 + a_koff;
            const uint32_t kbf = kk * 32 + b_koff;
            uint32_t ahi[4][4], alo[4][4], bhi[4][2], blo[4][2];
#pragma unroll
            for (int mt = 0; mt < 4; mt++) {
                ldsm_x4(ahi[mt], bb + GOFF_AHI + (a_row + mt * 16) * GROWB + ka);
                ldsm_x4(alo[mt], bb + GOFF_ALO + (a_row + mt * 16) * GROWB + ka);
            }
#pragma unroll
            for (int nt = 0; nt < 4; nt++) {
                ldsm_x2(bhi[nt], bb + GOFF_BHI + (b_row + nt * 8) * GROWB + kbf);
                ldsm_x2(blo[nt], bb + GOFF_BLO + (b_row + nt * 8) * GROWB + kbf);
            }
#pragma unroll
            for (int mt = 0; mt < 4; mt++)
#pragma unroll
                for (int nt = 0; nt < 4; nt++) {
                    mma_bf16(acc[mt][nt], ahi[mt], bhi[nt]);
                    mma_bf16(acc[mt][nt], ahi[mt], blo[nt]);
                    mma_bf16(acc[mt][nt], alo[mt], bhi[nt]);
                }
        }
        __syncthreads();
    }

    // epilogue: acc + bias -> C (fragment layout of m16n8k16)
#pragma unroll
    for (int nt = 0; nt < 4; nt++) {
        const int n = n0 + wn * 32 + nt * 8 + (lane & 3) * 2;
        const float b0 = bias[n], b1 = bias[n + 1];
#pragma unroll
        for (int mt = 0; mt < 4; mt++) {
            const int m = m0 + wm * 64 + mt * 16 + (lane >> 2);
            *(float2*)&C[(size_t)m * GKD + n] =
                make_float2(acc[mt][nt][0] + b0, acc[mt][nt][1] + b1);
            *(float2*)&C[(size_t)(m + 8) * GKD + n] =
                make_float2(acc[mt][nt][2] + b0, acc[mt][nt][3] + b1);
        }
    }
#undef GISSUE
}

// ---------------------------------------------------------------------------
// Fused flash attention (unchanged, known-correct): S = Kh Kh^T / sqrt(768),
// row mask, online softmax, O = P @ Kh.
// ---------------------------------------------------------------------------
#define ATTN_SMEM_FLOATS (64 * 132 + 64 * 68 + 64 * 68 + 128 * 64)
#define ATTN_SMEM_BYTES  (ATTN_SMEM_FLOATS * 4)

__global__ __launch_bounds__(256, 2)
void attn_kernel(const float* __restrict__ gK, const int* __restrict__ mask,
                 float* __restrict__ out) {
    extern __shared__ float smf[];
    float* QsT = smf;
    float* KsT = QsT + 64 * 132;
    float* Ksm = KsT + 64 * 68;
    float* Ps  = Ksm + 64 * 68;
    __shared__ int mrow[128];

    const int q0 = blockIdx.x * 128;
    const int h  = blockIdx.y;
    const int b  = blockIdx.z;
    const int tid = threadIdx.x;
    const int tx = tid & 15;
    const int ty = tid >> 4;

    const float* Kb = gK + ((size_t)b * L_) * D_ + h * DH_;

    {
        int d = tid & 63, q = tid >> 6;
#pragma unroll
        for (int i = 0; i < 32; i++) {
            int qq = q + i * 4;
            QsT[d * 132 + qq] = Kb[(size_t)(q0 + qq) * D_ + d];
        }
    }
    if (tid < 128) mrow[tid] = mask[b * L_ + q0 + tid];
    __syncthreads();

    float m_i[8], l_i[8], o[8][4];
#pragma unroll
    for (int i = 0; i < 8; i++) {
        m_i[i] = NEG_BIG; l_i[i] = 0.f;
#pragma unroll
        for (int j = 0; j < 4; j++) o[i][j] = 0.f;
    }
    bool rmask[8];
#pragma unroll
    for (int i = 0; i < 8; i++) rmask[i] = (mrow[ty * 8 + i] == 0);

    const float scale = 0.03608439182435161f;

    for (int kt = 0; kt < L_; kt += 64) {
        __syncthreads();
        {
            int d = tid & 63, k = tid >> 6;
#pragma unroll
            for (int i = 0; i < 16; i++) {
                int kk = k + i * 4;
                float v = Kb[(size_t)(kt + kk) * D_ + d];
                Ksm[kk * 68 + d] = v;
                KsT[d * 68 + kk] = v;
            }
        }
        __syncthreads();

        float s[8][4];
#pragma unroll
        for (int i = 0; i < 8; i++)
#pragma unroll
            for (int j = 0; j < 4; j++) s[i][j] = 0.f;

#pragma unroll 4
        for (int d = 0; d < 64; d++) {
            float4 a0 = *(const float4*)&QsT[d * 132 + ty * 8];
            float4 a1 = *(const float4*)&QsT[d * 132 + ty * 8 + 4];
            float4 b4 = *(const float4*)&KsT[d * 68 + tx * 4];
            float av[8] = {a0.x, a0.y, a0.z, a0.w, a1.x, a1.y, a1.z, a1.w};
            float bv[4] = {b4.x, b4.y, b4.z, b4.w};
#pragma unroll
            for (int i = 0; i < 8; i++)
#pragma unroll
                for (int j = 0; j < 4; j++)
                    s[i][j] = fmaf(av[i], bv[j], s[i][j]);
        }

#pragma unroll
        for (int i = 0; i < 8; i++) {
            float rm = NEG_BIG;
#pragma unroll
            for (int j = 0; j < 4; j++) {
                s[i][j] = rmask[i] ? -1e9f : s[i][j] * scale;
                rm = fmaxf(rm, s[i][j]);
            }
            rm = fmaxf(rm, __shfl_xor_sync(0xffffffffu, rm, 1));
            rm = fmaxf(rm, __shfl_xor_sync(0xffffffffu, rm, 2));
            rm = fmaxf(rm, __shfl_xor_sync(0xffffffffu, rm, 4));
            rm = fmaxf(rm, __shfl_xor_sync(0xffffffffu, rm, 8));
            float nm   = fmaxf(m_i[i], rm);
            float corr = __expf(m_i[i] - nm);
            m_i[i] = nm;
            float ps = 0.f;
#pragma unroll
            for (int j = 0; j < 4; j++) {
                s[i][j] = __expf(s[i][j] - nm);
                ps += s[i][j];
            }
            ps += __shfl_xor_sync(0xffffffffu, ps, 1);
            ps += __shfl_xor_sync(0xffffffffu, ps, 2);
            ps += __shfl_xor_sync(0xffffffffu, ps, 4);
            ps += __shfl_xor_sync(0xffffffffu, ps, 8);
            l_i[i] = l_i[i] * corr + ps;
#pragma unroll
            for (int j = 0; j < 4; j++) o[i][j] *= corr;
            *(float4*)&Ps[(ty * 8 + i) * 64 + tx * 4] =
                make_float4(s[i][0], s[i][1], s[i][2], s[i][3]);
        }
        __syncthreads();

#pragma unroll 2
        for (int k = 0; k < 64; k += 4) {
            float4 v0 = *(const float4*)&Ksm[(k + 0) * 68 + tx * 4];
            float4 v1 = *(const float4*)&Ksm[(k + 1) * 68 + tx * 4];
            float4 v2 = *(const float4*)&Ksm[(k + 2) * 68 + tx * 4];
            float4 v3 = *(const float4*)&Ksm[(k + 3) * 68 + tx * 4];
#pragma unroll
            for (int i = 0; i < 8; i++) {
                float4 p4 = *(const float4*)&Ps[(ty * 8 + i) * 64 + k];
                o[i][0] = fmaf(p4.x, v0.x, o[i][0]);
                o[i][1] = fmaf(p4.x, v0.y, o[i][1]);
                o[i][2] = fmaf(p4.x, v0.z, o[i][2]);
                o[i][3] = fmaf(p4.x, v0.w, o[i][3]);
                o[i][0] = fmaf(p4.y, v1.x, o[i][0]);
                o[i][1] = fmaf(p4.y, v1.y, o[i][1]);
                o[i][2] = fmaf(p4.y, v1.z, o[i][2]);
                o[i][3] = fmaf(p4.y, v1.w, o[i][3]);
                o[i][0] = fmaf(p4.z, v2.x, o[i][0]);
                o[i][1] = fmaf(p4.z, v2.y, o[i][1]);
                o[i][2] = fmaf(p4.z, v2.z, o[i][2]);
                o[i][3] = fmaf(p4.z, v2.w, o[i][3]);
                o[i][0] = fmaf(p4.w, v3.x, o[i][0]);
                o[i][1] = fmaf(p4.w, v3.y, o[i][1]);
                o[i][2] = fmaf(p4.w, v3.z, o[i][2]);
                o[i][3] = fmaf(p4.w, v3.w, o[i][3]);
            }
        }
    }

#pragma unroll
    for (int i = 0; i < 8; i++) {
        float inv = 1.0f / l_i[i];
        int q = q0 + ty * 8 + i;
        float4 r = make_float4(o[i][0] * inv, o[i][1] * inv,
                               o[i][2] * inv, o[i][3] * inv);
        *(float4*)&out[((size_t)b * L_ + q) * D_ + h * DH_ + tx * 4] = r;
    }
}

// ---------------------------------------------------------------------------
// Launch. Inputs: 0:x 1:mask 2:Wq 3:bq 4:Wk 5:bk 6:Wv 7:bv 8:Wo 9:bo
// (Q projection and Wv/bv are dead in the reference: V = K, scores = K K^T.)
// ---------------------------------------------------------------------------
extern "C" void kernel_launch(void* const* d_in, const int* in_sizes, int n_in,
                              void* d_out, int out_size) {
    const float* x    = (const float*)d_in[0];
    const int*   mask = (const int*)  d_in[1];
    const float* Wk   = (const float*)d_in[4];
    const float* bk   = (const float*)d_in[5];
    const float* Wo   = (const float*)d_in[8];
    const float* bo   = (const float*)d_in[9];
    float* out = (float*)d_out;

    float *pK, *pwV;
    __nv_bfloat16 *pxhi, *pxlo, *pvhi, *pvlo, *pwkhi, *pwklo, *pwohi, *pwolo;
    cudaGetSymbolAddress((void**)&pK,    g_K);
    cudaGetSymbolAddress((void**)&pwV,   g_wV);
    cudaGetSymbolAddress((void**)&pxhi,  g_xhi);
    cudaGetSymbolAddress((void**)&pxlo,  g_xlo);
    cudaGetSymbolAddress((void**)&pvhi,  g_vhi);
    cudaGetSymbolAddress((void**)&pvlo,  g_vlo);
    cudaGetSymbolAddress((void**)&pwkhi, g_wkhi);
    cudaGetSymbolAddress((void**)&pwklo, g_wklo);
    cudaGetSymbolAddress((void**)&pwohi, g_wohi);
    cudaGetSymbolAddress((void**)&pwolo, g_wolo);

    cudaFuncSetAttribute(attn_kernel,
                         cudaFuncAttributeMaxDynamicSharedMemorySize,
                         ATTN_SMEM_BYTES);
    cudaFuncSetAttribute(gemm_mma_split,
                         cudaFuncAttributeMaxDynamicSharedMemorySize,
                         GSMEM_TOTAL);

    const int M = B_ * L_;                    // 8192
    const int nx4 = M * D_ / 4;
    const int nw4 = D_ * D_ / 4;

    // splits
    split_fp32<<<(nx4 + 255) / 256, 256>>>(x,  pxhi,  pxlo,  nx4);
    split_fp32<<<(nw4 + 255) / 256, 256>>>(Wk, pwkhi, pwklo, nw4);
    split_fp32<<<(nw4 + 255) / 256, 256>>>(Wo, pwohi, pwolo, nw4);

    // 1) K = x @ Wk^T + bk  (tensor cores via mma.sync)
    {
        dim3 grid(D_ / 128, M / 128);
        gemm_mma_split<<<grid, 256, GSMEM_TOTAL>>>(pxhi, pxlo, pwkhi, pwklo,
                                                   bk, pK);
    }
    // 2) fused attention
    {
        dim3 grid(L_ / 128, H_, B_);
        attn_kernel<<<grid, 256, ATTN_SMEM_BYTES>>>(pK, mask, pwV);
    }
    // 3) out = wV @ Wo^T + bo  (tensor cores via mma.sync)
    split_fp32<<<(nx4 + 255) / 256, 256>>>(pwV, pvhi, pvlo, nx4);
    {
        dim3 grid(D_ / 128, M / 128);
        gemm_mma_split<<<grid, 256, GSMEM_TOTAL>>>(pvhi, pvlo, pwohi, pwolo,
                                                   bo, out);
    }
}

// round 8
// speedup vs baseline: 2.4644x; 1.8278x over previous
#include <cuda_runtime.h>
#include <cuda_bf16.h>
#include <cstdint>

#define B_  8
#define L_  1024
#define D_  768
#define H_  12
#define DH_ 64

// ---------------- scratch (__device__ globals; no allocation allowed) ------
__device__ __nv_bfloat16 g_xhi [B_ * L_ * D_];   // split of x
__device__ __nv_bfloat16 g_xlo [B_ * L_ * D_];
__device__ __nv_bfloat16 g_khi [B_ * L_ * D_];   // split of K projection
__device__ __nv_bfloat16 g_klo [B_ * L_ * D_];
__device__ __nv_bfloat16 g_vhi [B_ * L_ * D_];   // split of attention output
__device__ __nv_bfloat16 g_vlo [B_ * L_ * D_];
__device__ __nv_bfloat16 g_wkhi[D_ * D_];
__device__ __nv_bfloat16 g_wklo[D_ * D_];
__device__ __nv_bfloat16 g_wohi[D_ * D_];
__device__ __nv_bfloat16 g_wolo[D_ * D_];

// ---------------------------------------------------------------------------
// helpers
// ---------------------------------------------------------------------------
__device__ __forceinline__ uint32_t smem_u32(const void* p) {
    uint32_t a;
    asm("{ .reg .u64 t; cvta.to.shared.u64 t, %1; cvt.u32.u64 %0, t; }"
        : "=r"(a) : "l"(p));
    return a;
}
__device__ __forceinline__ void ldsm_x4(uint32_t* r, uint32_t addr) {
    asm volatile("ldmatrix.sync.aligned.m8n8.x4.shared.b16 {%0,%1,%2,%3}, [%4];"
                 : "=r"(r[0]), "=r"(r[1]), "=r"(r[2]), "=r"(r[3]) : "r"(addr));
}
__device__ __forceinline__ void ldsm_x4t(uint32_t* r, uint32_t addr) {
    asm volatile("ldmatrix.sync.aligned.m8n8.x4.trans.shared.b16 {%0,%1,%2,%3}, [%4];"
                 : "=r"(r[0]), "=r"(r[1]), "=r"(r[2]), "=r"(r[3]) : "r"(addr));
}
__device__ __forceinline__ void mma_bf16(float* c, const uint32_t* a,
                                         const uint32_t* b) {
    asm volatile(
        "mma.sync.aligned.m16n8k16.row.col.f32.bf16.bf16.f32 "
        "{%0,%1,%2,%3}, {%4,%5,%6,%7}, {%8,%9}, {%0,%1,%2,%3};"
        : "+f"(c[0]), "+f"(c[1]), "+f"(c[2]), "+f"(c[3])
        : "r"(a[0]), "r"(a[1]), "r"(a[2]), "r"(a[3]), "r"(b[0]), "r"(b[1]));
}
__device__ __forceinline__ float ex2f(float x) {
    float r;
    asm("ex2.approx.f32 %0, %1;" : "=f"(r) : "f"(x));
    return r;
}
// pack two fp32 into bf16x2: low element = l, high = h
__device__ __forceinline__ uint32_t packbf(float l, float h) {
    uint32_t r;
    asm("cvt.rn.bf16x2.f32 %0, %1, %2;" : "=r"(r) : "f"(h), "f"(l));
    return r;
}
__device__ __forceinline__ float lowf(uint32_t u) { return __uint_as_float(u << 16); }
__device__ __forceinline__ float hif(uint32_t u)  { return __uint_as_float(u & 0xFFFF0000u); }

#define CP_ASYNC16(saddr, gaddr) \
    asm volatile("cp.async.ca.shared.global [%0], [%1], 16;" \
                 :: "r"(saddr), "l"(gaddr) : "memory")
#define CP_COMMIT() asm volatile("cp.async.commit_group;" ::: "memory")
#define CP_WAIT(n)  asm volatile("cp.async.wait_group %0;" :: "n"(n) : "memory")

// ---------------------------------------------------------------------------
// split: fp32 -> (hi bf16, lo bf16)
// ---------------------------------------------------------------------------
__global__ void split_fp32(const float* __restrict__ in,
                           __nv_bfloat16* __restrict__ hi,
                           __nv_bfloat16* __restrict__ lo, int n4) {
    int i = blockIdx.x * blockDim.x + threadIdx.x;
    if (i >= n4) return;
    float4 v = ((const float4*)in)[i];
    uint32_t h0 = packbf(v.x, v.y), h1 = packbf(v.z, v.w);
    uint32_t l0 = packbf(v.x - lowf(h0), v.y - hif(h0));
    uint32_t l1 = packbf(v.z - lowf(h1), v.w - hif(h1));
    ((uint2*)hi)[i] = make_uint2(h0, h1);
    ((uint2*)lo)[i] = make_uint2(l0, l1);
}

// ---------------------------------------------------------------------------
// split-bf16 tensor-core GEMM: C[M,768] = A[M,768] * W[768,768]^T + bias
// CTA 128x128, K-block 32, 8 warps (2Mx4N), double-buffered cp.async.
// Output: fp32 (Cf) or split bf16 (Chi/Clo).
// ---------------------------------------------------------------------------
#define GKD    768
#define GROWB  80
#define GOFF_AHI 0
#define GOFF_ALO 10240
#define GOFF_BHI 20480
#define GOFF_BLO 30720
#define GBUF   40960
#define GSMEM_TOTAL (2 * GBUF)

__global__ __launch_bounds__(256)
void gemm_mma_split(const __nv_bfloat16* __restrict__ Ahi,
                    const __nv_bfloat16* __restrict__ Alo,
                    const __nv_bfloat16* __restrict__ Bhi,
                    const __nv_bfloat16* __restrict__ Blo,
                    const float* __restrict__ bias,
                    float* __restrict__ Cf,
                    __nv_bfloat16* __restrict__ Chi,
                    __nv_bfloat16* __restrict__ Clo) {
    extern __shared__ char smc[];
    const uint32_t sb = smem_u32(smc);
    const int tid  = threadIdx.x;
    const int lane = tid & 31;
    const int wid  = tid >> 5;
    const int wm   = wid & 1;
    const int wn   = wid >> 1;
    const int m0 = blockIdx.y * 128;
    const int n0 = blockIdx.x * 128;

    const char* gp[4] = {
        (const char*)(Ahi + (size_t)m0 * GKD),
        (const char*)(Alo + (size_t)m0 * GKD),
        (const char*)(Bhi + (size_t)n0 * GKD),
        (const char*)(Blo + (size_t)n0 * GKD)};
    const uint32_t soff[4] = {GOFF_AHI, GOFF_ALO, GOFF_BHI, GOFF_BLO};

    const int r0c = (tid * 2) >> 2, c0c = (tid * 2) & 3;
    const int r1c = (tid * 2 + 1) >> 2, c1c = (tid * 2 + 1) & 3;

#define GISSUE(kb, buf) do {                                                   \
    const uint32_t bb = sb + (buf) * GBUF;                                     \
    _Pragma("unroll")                                                          \
    for (int mat = 0; mat < 4; mat++) {                                        \
        CP_ASYNC16(bb + soff[mat] + r0c * GROWB + c0c * 16,                    \
                   gp[mat] + (size_t)r0c * (GKD * 2) + (kb) * 64 + c0c * 16);  \
        CP_ASYNC16(bb + soff[mat] + r1c * GROWB + c1c * 16,                    \
                   gp[mat] + (size_t)r1c * (GKD * 2) + (kb) * 64 + c1c * 16);  \
    }                                                                          \
    CP_COMMIT();                                                               \
} while (0)

    float acc[4][4][4];
#pragma unroll
    for (int mt = 0; mt < 4; mt++)
#pragma unroll
        for (int nt = 0; nt < 4; nt++)
#pragma unroll
            for (int k = 0; k < 4; k++) acc[mt][nt][k] = 0.f;

    const uint32_t a_row  = wm * 64 + (lane & 15);
    const uint32_t a_koff = (lane >> 4) << 4;
    const uint32_t b_row  = wn * 32 + (lane & 7);
    const uint32_t b_koff = ((lane >> 3) & 1) << 4;

    GISSUE(0, 0);

    for (int kb = 0; kb < GKD / 32; kb++) {
        const int buf = kb & 1;
        if (kb + 1 < GKD / 32) {
            GISSUE(kb + 1, buf ^ 1);
            CP_WAIT(1);
        } else {
            CP_WAIT(0);
        }
        __syncthreads();

        const uint32_t bb = sb + buf * GBUF;
#pragma unroll
        for (int kk = 0; kk < 2; kk++) {
            const uint32_t ka = kk * 32 + a_koff;
            const uint32_t kbf = kk * 32 + b_koff;
            uint32_t ahi[4][4], alo[4][4], bhi[4][2], blo[4][2];
#pragma unroll
            for (int mt = 0; mt < 4; mt++) {
                ldsm_x4(ahi[mt], bb + GOFF_AHI + (a_row + mt * 16) * GROWB + ka);
                ldsm_x4(alo[mt], bb + GOFF_ALO + (a_row + mt * 16) * GROWB + ka);
            }
#pragma unroll
            for (int nt = 0; nt < 4; nt++) {
                asm volatile("ldmatrix.sync.aligned.m8n8.x2.shared.b16 {%0,%1}, [%2];"
                             : "=r"(bhi[nt][0]), "=r"(bhi[nt][1])
                             : "r"(bb + GOFF_BHI + (b_row + nt * 8) * GROWB + kbf));
                asm volatile("ldmatrix.sync.aligned.m8n8.x2.shared.b16 {%0,%1}, [%2];"
                             : "=r"(blo[nt][0]), "=r"(blo[nt][1])
                             : "r"(bb + GOFF_BLO + (b_row + nt * 8) * GROWB + kbf));
            }
#pragma unroll
            for (int mt = 0; mt < 4; mt++)
#pragma unroll
                for (int nt = 0; nt < 4; nt++) {
                    mma_bf16(acc[mt][nt], ahi[mt], bhi[nt]);
                    mma_bf16(acc[mt][nt], ahi[mt], blo[nt]);
                    mma_bf16(acc[mt][nt], alo[mt], bhi[nt]);
                }
        }
        __syncthreads();
    }

    // epilogue
#pragma unroll
    for (int nt = 0; nt < 4; nt++) {
        const int n = n0 + wn * 32 + nt * 8 + (lane & 3) * 2;
        const float b0 = bias[n], b1 = bias[n + 1];
#pragma unroll
        for (int mt = 0; mt < 4; mt++) {
            const int m = m0 + wm * 64 + mt * 16 + (lane >> 2);
            const float v00 = acc[mt][nt][0] + b0, v01 = acc[mt][nt][1] + b1;
            const float v10 = acc[mt][nt][2] + b0, v11 = acc[mt][nt][3] + b1;
            if (Cf) {
                *(float2*)&Cf[(size_t)m * GKD + n] = make_float2(v00, v01);
                *(float2*)&Cf[(size_t)(m + 8) * GKD + n] = make_float2(v10, v11);
            } else {
                uint32_t h0 = packbf(v00, v01);
                uint32_t l0 = packbf(v00 - lowf(h0), v01 - hif(h0));
                uint32_t h1 = packbf(v10, v11);
                uint32_t l1 = packbf(v10 - lowf(h1), v11 - hif(h1));
                *(uint32_t*)&Chi[(size_t)m * GKD + n] = h0;
                *(uint32_t*)&Clo[(size_t)m * GKD + n] = l0;
                *(uint32_t*)&Chi[(size_t)(m + 8) * GKD + n] = h1;
                *(uint32_t*)&Clo[(size_t)(m + 8) * GKD + n] = l1;
            }
        }
    }
#undef GISSUE
}

// ---------------------------------------------------------------------------
// mma.sync flash attention, split-bf16.
// Per (b,h): S = Kh Kh^T / sqrt(768) (row mask), softmax, O = P @ Kh.
// CTA: 128 q-rows, 8 warps x 16 rows. K streamed in 128-key tiles, 2-stage
// cp.async. SMEM pitch 144B (72 bf16) -> conflict-free ldmatrix.
// Writes O split into (Vhi, Vlo) bf16 for the following GEMM.
// ---------------------------------------------------------------------------
#define APITCH 144
#define ASQH   0
#define ASQL   18432
#define ASK    36864            // + buf*36864 ; lo at +18432
#define ASMEM_TOTAL (36864 + 2 * 36864)

__global__ __launch_bounds__(256)
void attn_mma(const __nv_bfloat16* __restrict__ Khi,
              const __nv_bfloat16* __restrict__ Klo,
              const int* __restrict__ mask,
              __nv_bfloat16* __restrict__ Vhi,
              __nv_bfloat16* __restrict__ Vlo) {
    extern __shared__ char smc[];
    const uint32_t sb = smem_u32(smc);
    const int tid  = threadIdx.x;
    const int lane = tid & 31;
    const int w    = tid >> 5;
    const int q0 = blockIdx.x * 128;
    const int h  = blockIdx.y;
    const int b  = blockIdx.z;

    const size_t gk = ((size_t)b * L_) * D_ + h * DH_;      // K base (row 0)
    const size_t gq = gk + (size_t)q0 * D_;                 // Q tile base

    // chunk coords for cp.async: 1024 chunks/matrix, 4 per thread
    const int crow[4] = {(tid + 0) >> 3, (tid + 256) >> 3,
                         (tid + 512) >> 3, (tid + 768) >> 3};
    const int ccol[4] = {(tid + 0) & 7, (tid + 256) & 7,
                         (tid + 512) & 7, (tid + 768) & 7};

#define AISSUE_K(kt, buf) do {                                                 \
    const uint32_t dh = sb + ASK + (buf) * 36864;                              \
    const __nv_bfloat16* ghx = Khi + gk + (size_t)(kt) * 128 * D_;             \
    const __nv_bfloat16* glx = Klo + gk + (size_t)(kt) * 128 * D_;             \
    _Pragma("unroll")                                                          \
    for (int i = 0; i < 4; i++) {                                              \
        const uint32_t so = crow[i] * APITCH + ccol[i] * 16;                   \
        const size_t go = (size_t)crow[i] * D_ + ccol[i] * 8;                  \
        CP_ASYNC16(dh + so, (const char*)(ghx + go));                          \
        CP_ASYNC16(dh + 18432 + so, (const char*)(glx + go));                  \
    }                                                                          \
    CP_COMMIT();                                                               \
} while (0)

    // issue Q (group), then K0, K1
    {
#pragma unroll
        for (int i = 0; i < 4; i++) {
            const uint32_t so = crow[i] * APITCH + ccol[i] * 16;
            const size_t go = (size_t)crow[i] * D_ + ccol[i] * 8;
            CP_ASYNC16(sb + ASQH + so, (const char*)(Khi + gq + go));
            CP_ASYNC16(sb + ASQL + so, (const char*)(Klo + gq + go));
        }
        CP_COMMIT();
    }
    AISSUE_K(0, 0);
    AISSUE_K(1, 1);

    CP_WAIT(2);
    __syncthreads();

    // Q fragments (held for the whole kernel)
    uint32_t qh[4][4], ql[4][4];
#pragma unroll
    for (int ks = 0; ks < 4; ks++) {
        const uint32_t a = sb + ASQH + (w * 16 + (lane & 15)) * APITCH +
                           ks * 32 + ((lane >> 4) << 4);
        ldsm_x4(qh[ks], a);
        ldsm_x4(ql[ks], a + 18432);
    }

    const bool rm0 = (__ldg(&mask[b * L_ + q0 + w * 16 + (lane >> 2)]) == 0);
    const bool rm1 = (__ldg(&mask[b * L_ + q0 + w * 16 + (lane >> 2) + 8]) == 0);
    const float kscale = 0.03608439182435161f * 1.4426950408889634f;

    float m0 = -3e38f, m1 = -3e38f, l0 = 0.f, l1 = 0.f;
    float o[8][4];
#pragma unroll
    for (int dn = 0; dn < 8; dn++)
#pragma unroll
        for (int j = 0; j < 4; j++) o[dn][j] = 0.f;

    for (int kt = 0; kt < L_ / 128; kt++) {
        if (kt < L_ / 128 - 1) { CP_WAIT(1); } else { CP_WAIT(0); }
        __syncthreads();
        const uint32_t kb = sb + ASK + (kt & 1) * 36864;

        // ---- S = Q K^T (split, fp32 accum) ----
        float s[16][4];
#pragma unroll
        for (int nb = 0; nb < 16; nb++)
#pragma unroll
            for (int j = 0; j < 4; j++) s[nb][j] = 0.f;

#pragma unroll
        for (int nb = 0; nb < 16; nb++) {
            uint32_t bh[8], bl[8];
            const uint32_t a0 = kb + (nb * 8 + (lane & 7)) * APITCH +
                                ((lane >> 3) << 4);
            ldsm_x4(bh, a0);
            ldsm_x4(bh + 4, a0 + 64);
            ldsm_x4(bl, a0 + 18432);
            ldsm_x4(bl + 4, a0 + 18432 + 64);
#pragma unroll
            for (int ks = 0; ks < 4; ks++) {
                mma_bf16(s[nb], qh[ks], bh + ks * 2);
                mma_bf16(s[nb], qh[ks], bl + ks * 2);
                mma_bf16(s[nb], ql[ks], bh + ks * 2);
            }
        }

        // ---- online softmax (exp2 domain, scale pre-folded) ----
        float tm0 = -3e38f, tm1 = -3e38f;
#pragma unroll
        for (int nb = 0; nb < 16; nb++) {
            s[nb][0] = rm0 ? -1e9f : s[nb][0] * kscale;
            s[nb][1] = rm0 ? -1e9f : s[nb][1] * kscale;
            s[nb][2] = rm1 ? -1e9f : s[nb][2] * kscale;
            s[nb][3] = rm1 ? -1e9f : s[nb][3] * kscale;
            tm0 = fmaxf(tm0, fmaxf(s[nb][0], s[nb][1]));
            tm1 = fmaxf(tm1, fmaxf(s[nb][2], s[nb][3]));
        }
        tm0 = fmaxf(tm0, __shfl_xor_sync(0xffffffffu, tm0, 1));
        tm0 = fmaxf(tm0, __shfl_xor_sync(0xffffffffu, tm0, 2));
        tm1 = fmaxf(tm1, __shfl_xor_sync(0xffffffffu, tm1, 1));
        tm1 = fmaxf(tm1, __shfl_xor_sync(0xffffffffu, tm1, 2));
        const float nm0 = fmaxf(m0, tm0), nm1 = fmaxf(m1, tm1);
        const float c0 = ex2f(m0 - nm0), c1 = ex2f(m1 - nm1);
        m0 = nm0; m1 = nm1;

        float ts0 = 0.f, ts1 = 0.f;
#pragma unroll
        for (int nb = 0; nb < 16; nb++) {
            s[nb][0] = ex2f(s[nb][0] - nm0);
            s[nb][1] = ex2f(s[nb][1] - nm0);
            s[nb][2] = ex2f(s[nb][2] - nm1);
            s[nb][3] = ex2f(s[nb][3] - nm1);
            ts0 += s[nb][0] + s[nb][1];
            ts1 += s[nb][2] + s[nb][3];
        }
        l0 = l0 * c0 + ts0;
        l1 = l1 * c1 + ts1;
#pragma unroll
        for (int dn = 0; dn < 8; dn++) {
            o[dn][0] *= c0; o[dn][1] *= c0;
            o[dn][2] *= c1; o[dn][3] *= c1;
        }

        // ---- O += P @ V (V = K tile), P split hi/lo in registers ----
#pragma unroll
        for (int kk = 0; kk < 8; kk++) {
            uint32_t ph[4], pl[4];
            {
                const float* sA = s[kk * 2];
                const float* sB = s[kk * 2 + 1];
                ph[0] = packbf(sA[0], sA[1]);
                ph[1] = packbf(sA[2], sA[3]);
                ph[2] = packbf(sB[0], sB[1]);
                ph[3] = packbf(sB[2], sB[3]);
                pl[0] = packbf(sA[0] - lowf(ph[0]), sA[1] - hif(ph[0]));
                pl[1] = packbf(sA[2] - lowf(ph[1]), sA[3] - hif(ph[1]));
                pl[2] = packbf(sB[0] - lowf(ph[2]), sB[1] - hif(ph[2]));
                pl[3] = packbf(sB[2] - lowf(ph[3]), sB[3] - hif(ph[3]));
            }
#pragma unroll
            for (int dn2 = 0; dn2 < 4; dn2++) {
                uint32_t vh[4], vl[4];
                const uint32_t a = kb + (kk * 16 + (lane & 15)) * APITCH +
                                   dn2 * 32 + ((lane >> 4) << 4);
                ldsm_x4t(vh, a);
                ldsm_x4t(vl, a + 18432);
                mma_bf16(o[dn2 * 2],     ph, vh);
                mma_bf16(o[dn2 * 2],     ph, vl);
                mma_bf16(o[dn2 * 2],     pl, vh);
                mma_bf16(o[dn2 * 2 + 1], ph, vh + 2);
                mma_bf16(o[dn2 * 2 + 1], ph, vl + 2);
                mma_bf16(o[dn2 * 2 + 1], pl, vh + 2);
            }
        }

        __syncthreads();
        if (kt + 2 < L_ / 128) AISSUE_K(kt + 2, kt & 1);
    }

    // ---- epilogue: normalize, split to bf16, store ----
    l0 += __shfl_xor_sync(0xffffffffu, l0, 1);
    l0 += __shfl_xor_sync(0xffffffffu, l0, 2);
    l1 += __shfl_xor_sync(0xffffffffu, l1, 1);
    l1 += __shfl_xor_sync(0xffffffffu, l1, 2);
    const float inv0 = 1.0f / l0, inv1 = 1.0f / l1;
    const int qa = q0 + w * 16 + (lane >> 2);
    const size_t ra = ((size_t)b * L_ + qa) * D_ + h * DH_;
    const size_t rb = ra + (size_t)8 * D_;
#pragma unroll
    for (int dn = 0; dn < 8; dn++) {
        const int col = dn * 8 + (lane & 3) * 2;
        const float v0 = o[dn][0] * inv0, v1 = o[dn][1] * inv0;
        const float v2 = o[dn][2] * inv1, v3 = o[dn][3] * inv1;
        uint32_t h0 = packbf(v0, v1);
        uint32_t l0p = packbf(v0 - lowf(h0), v1 - hif(h0));
        uint32_t h1 = packbf(v2, v3);
        uint32_t l1p = packbf(v2 - lowf(h1), v3 - hif(h1));
        *(uint32_t*)&Vhi[ra + col] = h0;
        *(uint32_t*)&Vlo[ra + col] = l0p;
        *(uint32_t*)&Vhi[rb + col] = h1;
        *(uint32_t*)&Vlo[rb + col] = l1p;
    }
#undef AISSUE_K
}

// ---------------------------------------------------------------------------
// Launch. Inputs: 0:x 1:mask 2:Wq 3:bq 4:Wk 5:bk 6:Wv 7:bv 8:Wo 9:bo
// (Q projection and Wv/bv are dead in the reference: V = K, scores = K K^T.)
// ---------------------------------------------------------------------------
extern "C" void kernel_launch(void* const* d_in, const int* in_sizes, int n_in,
                              void* d_out, int out_size) {
    const float* x    = (const float*)d_in[0];
    const int*   mask = (const int*)  d_in[1];
    const float* Wk   = (const float*)d_in[4];
    const float* bk   = (const float*)d_in[5];
    const float* Wo   = (const float*)d_in[8];
    const float* bo   = (const float*)d_in[9];
    float* out = (float*)d_out;

    __nv_bfloat16 *pxhi, *pxlo, *pkhi, *pklo, *pvhi, *pvlo;
    __nv_bfloat16 *pwkhi, *pwklo, *pwohi, *pwolo;
    cudaGetSymbolAddress((void**)&pxhi,  g_xhi);
    cudaGetSymbolAddress((void**)&pxlo,  g_xlo);
    cudaGetSymbolAddress((void**)&pkhi,  g_khi);
    cudaGetSymbolAddress((void**)&pklo,  g_klo);
    cudaGetSymbolAddress((void**)&pvhi,  g_vhi);
    cudaGetSymbolAddress((void**)&pvlo,  g_vlo);
    cudaGetSymbolAddress((void**)&pwkhi, g_wkhi);
    cudaGetSymbolAddress((void**)&pwklo, g_wklo);
    cudaGetSymbolAddress((void**)&pwohi, g_wohi);
    cudaGetSymbolAddress((void**)&pwolo, g_wolo);

    cudaFuncSetAttribute(gemm_mma_split,
                         cudaFuncAttributeMaxDynamicSharedMemorySize,
                         GSMEM_TOTAL);
    cudaFuncSetAttribute(attn_mma,
                         cudaFuncAttributeMaxDynamicSharedMemorySize,
                         ASMEM_TOTAL);

    const int M = B_ * L_;                    // 8192
    const int nx4 = M * D_ / 4;
    const int nw4 = D_ * D_ / 4;

    split_fp32<<<(nx4 + 255) / 256, 256>>>(x,  pxhi,  pxlo,  nx4);
    split_fp32<<<(nw4 + 255) / 256, 256>>>(Wk, pwkhi, pwklo, nw4);
    split_fp32<<<(nw4 + 255) / 256, 256>>>(Wo, pwohi, pwolo, nw4);

    // 1) K = x @ Wk^T + bk  -> written directly as split bf16
    {
        dim3 grid(D_ / 128, M / 128);
        gemm_mma_split<<<grid, 256, GSMEM_TOTAL>>>(pxhi, pxlo, pwkhi, pwklo,
                                                   bk, nullptr, pkhi, pklo);
    }
    // 2) fused flash attention on tensor cores -> split bf16 output
    {
        dim3 grid(L_ / 128, H_, B_);
        attn_mma<<<grid, 256, ASMEM_TOTAL>>>(pkhi, pklo, mask, pvhi, pvlo);
    }
    // 3) out = wV @ Wo^T + bo  -> fp32
    {
        dim3 grid(D_ / 128, M / 128);
        gemm_mma_split<<<grid, 256, GSMEM_TOTAL>>>(pvhi, pvlo, pwohi, pwolo,
                                                   bo, out, nullptr, nullptr);
    }
}